// round 4
// baseline (speedup 1.0000x reference)
#include <cuda_runtime.h>
#include <cstddef>

#define NS 2000
#define NG 10000
#define NSOAP 6144

struct Ptrs { const float* v[6]; const float* g[6]; };

__constant__ float FAC[6] = {
    1.0f,
    0.5773502691896258f,   // 1/sqrt(3)
    0.4472135954999579f,   // 1/sqrt(5)
    0.3779644730092272f,   // 1/sqrt(7)
    0.3333333333333333f,   // 1/sqrt(9)
    0.30151134457776363f   // 1/sqrt(11)
};

// smem offset for l-block: sum_{l'<l} (2l'+1)*32 = 32*l*l
__device__ __forceinline__ constexpr int loff(int l) { return 32 * l * l; }

typedef unsigned long long u64;

__device__ __forceinline__ u64 fma2(u64 a, u64 b, u64 c) {
    u64 d;
    asm("fma.rn.f32x2 %0, %1, %2, %3;" : "=l"(d) : "l"(a), "l"(b), "l"(c));
    return d;
}
__device__ __forceinline__ u64 dup2(float x) {
    u64 d;
    asm("mov.b64 %0, {%1, %1};" : "=l"(d) : "f"(x));
    return d;
}
union U64F2 { u64 u; float2 f; };

// ---------------------------------------------------------------------------
// values tile: fully unrolled per-L Gram tile (lane = 8x4)
// ---------------------------------------------------------------------------
template <int L>
__device__ __forceinline__ void values_tile(const float* __restrict__ base,
                                            int a0, int b0,
                                            float* __restrict__ o) {
    constexpr int M = 2 * L + 1;
    float acc[8][4];
#pragma unroll
    for (int r = 0; r < 8; ++r)
#pragma unroll
        for (int c = 0; c < 4; ++c) acc[r][c] = 0.0f;

#pragma unroll
    for (int m = 0; m < M; ++m) {
        const float* row = base + m * 32;
        float4 a0v = *(const float4*)(row + a0);
        float4 a1v = *(const float4*)(row + a0 + 4);
        float4 bv  = *(const float4*)(row + b0);
        float av[8] = {a0v.x, a0v.y, a0v.z, a0v.w, a1v.x, a1v.y, a1v.z, a1v.w};
        float bb[4] = {bv.x, bv.y, bv.z, bv.w};
#pragma unroll
        for (int r = 0; r < 8; ++r)
#pragma unroll
            for (int c = 0; c < 4; ++c) acc[r][c] += av[r] * bb[c];
    }

    const float fac = FAC[L];
#pragma unroll
    for (int r = 0; r < 8; ++r) {
        float4 s = make_float4(fac * acc[r][0], fac * acc[r][1],
                               fac * acc[r][2], fac * acc[r][3]);
        __stcs((float4*)(o + r * 32), s);
    }
}

__global__ void __launch_bounds__(192) values_kernel(Ptrs p, float* __restrict__ out) {
    __shared__ __align__(16) float sv[1152];
    const int i = blockIdx.x;
    const int tid = threadIdx.x;

#pragma unroll
    for (int l = 0; l < 6; ++l) {
        const int cnt4 = (2 * l + 1) * 8;
        const float4* src = (const float4*)(p.v[l] + (size_t)i * (2 * l + 1) * 32);
        float4* dst = (float4*)(sv + loff(l));
        for (int j = tid; j < cnt4; j += 192) dst[j] = src[j];
    }
    __syncthreads();

    const int l = tid >> 5;
    const int lane = tid & 31;
    const int a0 = (lane >> 3) * 8;
    const int b0 = (lane & 7) * 4;
    float* o = out + (size_t)i * NSOAP + l * 1024 + a0 * 32 + b0;

    switch (l) {
        case 0: values_tile<0>(sv + loff(0), a0, b0, o); break;
        case 1: values_tile<1>(sv + loff(1), a0, b0, o); break;
        case 2: values_tile<2>(sv + loff(2), a0, b0, o); break;
        case 3: values_tile<3>(sv + loff(3), a0, b0, o); break;
        case 4: values_tile<4>(sv + loff(4), a0, b0, o); break;
        case 5: values_tile<5>(sv + loff(5), a0, b0, o); break;
    }
}

// ---------------------------------------------------------------------------
// grads tile: T[a,b] = sum_m ( g[m,a]*vg[m,b] + vg[m,a]*g[m,b] )
// lane = 8 rows x 4 cols, rows packed pairwise into f32x2 accumulators.
// Fully unrolled, compile-time M -> all smem offsets immediate.
// ---------------------------------------------------------------------------
template <int L>
__device__ __forceinline__ void grads_tile(const float* __restrict__ gb,
                                           const float* __restrict__ vb,
                                           int a0, int b0,
                                           float* __restrict__ o) {
    constexpr int M = 2 * L + 1;
    u64 acc[4][4];
#pragma unroll
    for (int r = 0; r < 4; ++r)
#pragma unroll
        for (int c = 0; c < 4; ++c) acc[r][c] = 0ull;

#pragma unroll
    for (int m = 0; m < M; ++m) {
        const float* rg = gb + m * 32;
        const float* rv = vb + m * 32;
        u64 ga2[4], va2[4];
#pragma unroll
        for (int r = 0; r < 4; ++r) {
            ga2[r] = *(const u64*)(rg + a0 + 2 * r);
            va2[r] = *(const u64*)(rv + a0 + 2 * r);
        }
        float4 gc4 = *(const float4*)(rg + b0);
        float4 vc4 = *(const float4*)(rv + b0);
        u64 gd[4] = {dup2(gc4.x), dup2(gc4.y), dup2(gc4.z), dup2(gc4.w)};
        u64 vd[4] = {dup2(vc4.x), dup2(vc4.y), dup2(vc4.z), dup2(vc4.w)};
#pragma unroll
        for (int r = 0; r < 4; ++r)
#pragma unroll
            for (int c = 0; c < 4; ++c) {
                acc[r][c] = fma2(ga2[r], vd[c], acc[r][c]);
                acc[r][c] = fma2(va2[r], gd[c], acc[r][c]);
            }
    }

#pragma unroll
    for (int r = 0; r < 4; ++r) {
        U64F2 u0, u1, u2, u3;
        u0.u = acc[r][0]; u1.u = acc[r][1]; u2.u = acc[r][2]; u3.u = acc[r][3];
        float4 lo = make_float4(u0.f.x, u1.f.x, u2.f.x, u3.f.x);
        float4 hi = make_float4(u0.f.y, u1.f.y, u2.f.y, u3.f.y);
        float* orow = o + (a0 + 2 * r) * 32 + b0;
        __stcs((float4*)orow, lo);
        __stcs((float4*)(orow + 32), hi);
    }
}

// ---------------------------------------------------------------------------
// grads: one block = TWO (i,x) pairs. 6 warps; warp w: pair pi=w/3, k=w%3,
// handles l=5-k then l=k -> every warp does exactly 12 m-steps.
// ---------------------------------------------------------------------------
__global__ void __launch_bounds__(192, 5) grads_kernel(Ptrs p,
                                                       const int* __restrict__ gidx,
                                                       float* __restrict__ out) {
    __shared__ __align__(16) float sg[2][1152];
    __shared__ __align__(16) float svg[2][1152];
    const int e0 = 2 * blockIdx.x;
    const int tid = threadIdx.x;

#pragma unroll
    for (int pi = 0; pi < 2; ++pi) {
        const int e = e0 + pi;
        const int s = gidx[e / 3];
#pragma unroll
        for (int l = 0; l < 6; ++l) {
            const int cnt4 = (2 * l + 1) * 8;
            const float4* gs = (const float4*)(p.g[l] + (size_t)e * (2 * l + 1) * 32);
            const float4* vs = (const float4*)(p.v[l] + (size_t)s * (2 * l + 1) * 32);
            const float fac = FAC[l];
            float4* dg = (float4*)(sg[pi] + loff(l));
            float4* dv = (float4*)(svg[pi] + loff(l));
            for (int j = tid; j < cnt4; j += 192) {
                dg[j] = __ldcs(gs + j);            // read-once: stream past L2
                float4 t = vs[j];                  // reused across blocks: keep in L2
                dv[j] = make_float4(fac * t.x, fac * t.y, fac * t.z, fac * t.w);
            }
        }
    }
    __syncthreads();

    const int w = tid >> 5;
    const int lane = tid & 31;
    const int pi = w / 3;
    const int k = w % 3;
    const int a0 = (lane >> 3) * 8;
    const int b0 = (lane & 7) * 4;
    const int e = e0 + pi;
    float* obase = out + (size_t)e * NSOAP;
    const float* SG = sg[pi];
    const float* SV = svg[pi];

    switch (k) {
        case 0:
            grads_tile<5>(SG + loff(5), SV + loff(5), a0, b0, obase + 5 * 1024);
            grads_tile<0>(SG + loff(0), SV + loff(0), a0, b0, obase + 0 * 1024);
            break;
        case 1:
            grads_tile<4>(SG + loff(4), SV + loff(4), a0, b0, obase + 4 * 1024);
            grads_tile<1>(SG + loff(1), SV + loff(1), a0, b0, obase + 1 * 1024);
            break;
        case 2:
            grads_tile<3>(SG + loff(3), SV + loff(3), a0, b0, obase + 3 * 1024);
            grads_tile<2>(SG + loff(2), SV + loff(2), a0, b0, obase + 2 * 1024);
            break;
    }
}

// ---------------------------------------------------------------------------
extern "C" void kernel_launch(void* const* d_in, const int* in_sizes, int n_in,
                              void* d_out, int out_size) {
    Ptrs p;
    const int* gidx = nullptr;
    for (int k = 0; k < n_in; ++k) {
        const int sz = in_sizes[k];
        if (sz == NG) { gidx = (const int*)d_in[k]; continue; }
        for (int l = 0; l < 6; ++l) {
            const int M = 2 * l + 1;
            if (sz == NS * M * 32)          p.v[l] = (const float*)d_in[k];
            else if (sz == NG * 3 * M * 32) p.g[l] = (const float*)d_in[k];
        }
    }
    float* out = (float*)d_out;

    values_kernel<<<NS, 192>>>(p, out);
    grads_kernel<<<NG * 3 / 2, 192>>>(p, gidx, out + (size_t)NS * NSOAP);
    (void)out_size;
}

// round 6
// speedup vs baseline: 1.0138x; 1.0138x over previous
#include <cuda_runtime.h>
#include <cstddef>

#define NS 2000
#define NG 10000
#define NSOAP 6144

struct Ptrs { const float* v[6]; const float* g[6]; };

__constant__ float FAC[6] = {
    1.0f,
    0.5773502691896258f,   // 1/sqrt(3)
    0.4472135954999579f,   // 1/sqrt(5)
    0.3779644730092272f,   // 1/sqrt(7)
    0.3333333333333333f,   // 1/sqrt(9)
    0.30151134457776363f   // 1/sqrt(11)
};

// smem offset for l-block: sum_{l'<l} (2l'+1)*32 = 32*l*l
__device__ __forceinline__ int loff(int l) { return 32 * l * l; }

typedef unsigned long long u64;

__device__ __forceinline__ u64 fma2(u64 a, u64 b, u64 c) {
    u64 d;
    asm("fma.rn.f32x2 %0, %1, %2, %3;" : "=l"(d) : "l"(a), "l"(b), "l"(c));
    return d;
}
__device__ __forceinline__ u64 dup2(float x) {
    u64 d;
    asm("mov.b64 %0, {%1, %1};" : "=l"(d) : "f"(x));
    return d;
}
union U64F2 { u64 u; float2 f; };

// ---------------------------------------------------------------------------
// values: out[i, l_block, a, b] = fac_l * sum_m v[i,m,a] * v[i,m,b]
// 1 block per i; 6 warps, warp w handles l=w; lane computes 8x4 tile.
// ---------------------------------------------------------------------------
__global__ void __launch_bounds__(192) values_kernel(Ptrs p, float* __restrict__ out) {
    __shared__ __align__(16) float sv[1152];
    const int i = blockIdx.x;
    const int tid = threadIdx.x;

#pragma unroll
    for (int l = 0; l < 6; ++l) {
        const int cnt4 = (2 * l + 1) * 8;
        const float4* src = (const float4*)(p.v[l] + (size_t)i * (2 * l + 1) * 32);
        float4* dst = (float4*)(sv + loff(l));
        for (int j = tid; j < cnt4; j += 192) dst[j] = src[j];
    }
    __syncthreads();

    const int l = tid >> 5;
    const int lane = tid & 31;
    const int a0 = (lane >> 3) * 8;
    const int b0 = (lane & 7) * 4;
    const float* base = sv + loff(l);
    const int M = 2 * l + 1;

    float acc[8][4];
#pragma unroll
    for (int r = 0; r < 8; ++r)
#pragma unroll
        for (int c = 0; c < 4; ++c) acc[r][c] = 0.0f;

    for (int m = 0; m < M; ++m) {
        const float* row = base + m * 32;
        float4 a0v = *(const float4*)(row + a0);
        float4 a1v = *(const float4*)(row + a0 + 4);
        float4 bv  = *(const float4*)(row + b0);
        float av[8] = {a0v.x, a0v.y, a0v.z, a0v.w, a1v.x, a1v.y, a1v.z, a1v.w};
        float bb[4] = {bv.x, bv.y, bv.z, bv.w};
#pragma unroll
        for (int r = 0; r < 8; ++r)
#pragma unroll
            for (int c = 0; c < 4; ++c) acc[r][c] += av[r] * bb[c];
    }

    const float fac = FAC[l];
    float* o = out + (size_t)i * NSOAP + l * 1024 + a0 * 32 + b0;
#pragma unroll
    for (int r = 0; r < 8; ++r) {
        float4 s = make_float4(fac * acc[r][0], fac * acc[r][1],
                               fac * acc[r][2], fac * acc[r][3]);
        __stcs((float4*)(o + r * 32), s);
    }
}

// ---------------------------------------------------------------------------
// grads tile: T[a,b] = sum_m ( g[m,a]*vg[m,b] + vg[m,a]*g[m,b] )
// lane = 8 rows x 4 cols; rows packed pairwise into f32x2 accumulators.
// Row operands loaded as 2x LDS.128 (ulonglong2 -> f32x2 pairs, no repack):
// 6 LDS per m-step instead of 10.
// ---------------------------------------------------------------------------
__device__ __forceinline__ void grads_tile(const float* __restrict__ gb,
                                           const float* __restrict__ vb,
                                           int M, int a0, int b0,
                                           float* __restrict__ o) {
    u64 acc[4][4];
#pragma unroll
    for (int r = 0; r < 4; ++r)
#pragma unroll
        for (int c = 0; c < 4; ++c) acc[r][c] = 0ull;

    for (int m = 0; m < M; ++m) {
        const float* rg = gb + m * 32;
        const float* rv = vb + m * 32;
        // row-pair operands: 2x LDS.128 each for g and v (32B, 16B-aligned)
        ulonglong2 gA = *(const ulonglong2*)(rg + a0);
        ulonglong2 gB = *(const ulonglong2*)(rg + a0 + 4);
        ulonglong2 vA = *(const ulonglong2*)(rv + a0);
        ulonglong2 vB = *(const ulonglong2*)(rv + a0 + 4);
        u64 ga2[4] = {gA.x, gA.y, gB.x, gB.y};
        u64 va2[4] = {vA.x, vA.y, vB.x, vB.y};
        // column operands: 1x LDS.128 each
        float4 gc4 = *(const float4*)(rg + b0);
        float4 vc4 = *(const float4*)(rv + b0);
        u64 gd[4] = {dup2(gc4.x), dup2(gc4.y), dup2(gc4.z), dup2(gc4.w)};
        u64 vd[4] = {dup2(vc4.x), dup2(vc4.y), dup2(vc4.z), dup2(vc4.w)};
#pragma unroll
        for (int r = 0; r < 4; ++r)
#pragma unroll
            for (int c = 0; c < 4; ++c) {
                acc[r][c] = fma2(ga2[r], vd[c], acc[r][c]);
                acc[r][c] = fma2(va2[r], gd[c], acc[r][c]);
            }
    }

#pragma unroll
    for (int r = 0; r < 4; ++r) {
        U64F2 u0, u1, u2, u3;
        u0.u = acc[r][0]; u1.u = acc[r][1]; u2.u = acc[r][2]; u3.u = acc[r][3];
        float4 lo = make_float4(u0.f.x, u1.f.x, u2.f.x, u3.f.x);
        float4 hi = make_float4(u0.f.y, u1.f.y, u2.f.y, u3.f.y);
        float* orow = o + (a0 + 2 * r) * 32 + b0;
        __stcs((float4*)orow, lo);
        __stcs((float4*)(orow + 32), hi);
    }
}

// ---------------------------------------------------------------------------
// grads: one block = TWO (i,x) pairs. 6 warps; warp w: pair pi=w/3, k=w%3,
// handles l=5-k then l=k -> every warp does exactly 12 m-steps.
// ---------------------------------------------------------------------------
__global__ void __launch_bounds__(192, 5) grads_kernel(Ptrs p,
                                                       const int* __restrict__ gidx,
                                                       float* __restrict__ out) {
    __shared__ __align__(16) float sg[2][1152];
    __shared__ __align__(16) float svg[2][1152];
    const int e0 = 2 * blockIdx.x;
    const int tid = threadIdx.x;

#pragma unroll
    for (int pi = 0; pi < 2; ++pi) {
        const int e = e0 + pi;
        const int s = gidx[e / 3];
#pragma unroll
        for (int l = 0; l < 6; ++l) {
            const int cnt4 = (2 * l + 1) * 8;
            const float4* gs = (const float4*)(p.g[l] + (size_t)e * (2 * l + 1) * 32);
            const float4* vs = (const float4*)(p.v[l] + (size_t)s * (2 * l + 1) * 32);
            const float fac = FAC[l];
            float4* dg = (float4*)(sg[pi] + loff(l));
            float4* dv = (float4*)(svg[pi] + loff(l));
            for (int j = tid; j < cnt4; j += 192) {
                dg[j] = __ldcs(gs + j);            // read-once: stream past L2
                float4 t = vs[j];                  // reused across blocks: keep in L2
                dv[j] = make_float4(fac * t.x, fac * t.y, fac * t.z, fac * t.w);
            }
        }
    }
    __syncthreads();

    const int w = tid >> 5;
    const int lane = tid & 31;
    const int pi = w / 3;
    const int k = w % 3;
    const int a0 = (lane >> 3) * 8;
    const int b0 = (lane & 7) * 4;
    const int e = e0 + pi;
    float* obase = out + (size_t)e * NSOAP;
    const float* SG = sg[pi];
    const float* SV = svg[pi];

    // first l-task: l = 5-k (M = 11-2k), then l = k (M = 2k+1)
    {
        const int l = 5 - k;
        grads_tile(SG + loff(l), SV + loff(l), 2 * l + 1, a0, b0, obase + l * 1024);
    }
    {
        const int l = k;
        grads_tile(SG + loff(l), SV + loff(l), 2 * l + 1, a0, b0, obase + l * 1024);
    }
}

// ---------------------------------------------------------------------------
extern "C" void kernel_launch(void* const* d_in, const int* in_sizes, int n_in,
                              void* d_out, int out_size) {
    Ptrs p;
    const int* gidx = nullptr;
    for (int k = 0; k < n_in; ++k) {
        const int sz = in_sizes[k];
        if (sz == NG) { gidx = (const int*)d_in[k]; continue; }
        for (int l = 0; l < 6; ++l) {
            const int M = 2 * l + 1;
            if (sz == NS * M * 32)          p.v[l] = (const float*)d_in[k];
            else if (sz == NG * 3 * M * 32) p.g[l] = (const float*)d_in[k];
        }
    }
    float* out = (float*)d_out;

    values_kernel<<<NS, 192>>>(p, out);
    grads_kernel<<<NG * 3 / 2, 192>>>(p, gidx, out + (size_t)NS * NSOAP);
    (void)out_size;
}

// round 8
// speedup vs baseline: 1.2610x; 1.2438x over previous
#include <cuda_runtime.h>
#include <cstddef>

#define NS 2000
#define NG 10000
#define NE 30000          // NG * 3 gradient entries
#define NSOAP 6144

struct Ptrs { const float* v[6]; const float* g[6]; };

__constant__ float FAC[6] = {
    1.0f,
    0.5773502691896258f,   // 1/sqrt(3)
    0.4472135954999579f,   // 1/sqrt(5)
    0.3779644730092272f,   // 1/sqrt(7)
    0.3333333333333333f,   // 1/sqrt(9)
    0.30151134457776363f   // 1/sqrt(11)
};

// smem offset for l-block: sum_{l'<l} (2l'+1)*32 = 32*l*l
__device__ __forceinline__ int loff(int l) { return 32 * l * l; }

typedef unsigned long long u64;

__device__ __forceinline__ u64 fma2(u64 a, u64 b, u64 c) {
    u64 d;
    asm("fma.rn.f32x2 %0, %1, %2, %3;" : "=l"(d) : "l"(a), "l"(b), "l"(c));
    return d;
}
__device__ __forceinline__ u64 dup2(float x) {
    u64 d;
    asm("mov.b64 %0, {%1, %1};" : "=l"(d) : "f"(x));
    return d;
}
union U64F2 { u64 u; float2 f; };

// ---------------------------------------------------------------------------
// grads tile: T[a,b] = sum_m ( g[m,a]*vg[m,b] + vg[m,a]*g[m,b] )
// lane = 8 rows x 4 cols; rows packed pairwise into f32x2 accumulators.
// Stores apply lane offsets (a0, b0) internally.
// ---------------------------------------------------------------------------
__device__ __forceinline__ void grads_tile(const float* __restrict__ gb,
                                           const float* __restrict__ vb,
                                           int M, int a0, int b0,
                                           float* __restrict__ o) {
    u64 acc[4][4];
#pragma unroll
    for (int r = 0; r < 4; ++r)
#pragma unroll
        for (int c = 0; c < 4; ++c) acc[r][c] = 0ull;

    for (int m = 0; m < M; ++m) {
        const float* rg = gb + m * 32;
        const float* rv = vb + m * 32;
        ulonglong2 gA = *(const ulonglong2*)(rg + a0);
        ulonglong2 gB = *(const ulonglong2*)(rg + a0 + 4);
        ulonglong2 vA = *(const ulonglong2*)(rv + a0);
        ulonglong2 vB = *(const ulonglong2*)(rv + a0 + 4);
        u64 ga2[4] = {gA.x, gA.y, gB.x, gB.y};
        u64 va2[4] = {vA.x, vA.y, vB.x, vB.y};
        float4 gc4 = *(const float4*)(rg + b0);
        float4 vc4 = *(const float4*)(rv + b0);
        u64 gd[4] = {dup2(gc4.x), dup2(gc4.y), dup2(gc4.z), dup2(gc4.w)};
        u64 vd[4] = {dup2(vc4.x), dup2(vc4.y), dup2(vc4.z), dup2(vc4.w)};
#pragma unroll
        for (int r = 0; r < 4; ++r)
#pragma unroll
            for (int c = 0; c < 4; ++c) {
                acc[r][c] = fma2(ga2[r], vd[c], acc[r][c]);
                acc[r][c] = fma2(va2[r], gd[c], acc[r][c]);
            }
    }

#pragma unroll
    for (int r = 0; r < 4; ++r) {
        U64F2 u0, u1, u2, u3;
        u0.u = acc[r][0]; u1.u = acc[r][1]; u2.u = acc[r][2]; u3.u = acc[r][3];
        float4 lo = make_float4(u0.f.x, u1.f.x, u2.f.x, u3.f.x);
        float4 hi = make_float4(u0.f.y, u1.f.y, u2.f.y, u3.f.y);
        float* orow = o + (a0 + 2 * r) * 32 + b0;
        __stcs((float4*)orow, lo);
        __stcs((float4*)(orow + 32), hi);
    }
}

// ---------------------------------------------------------------------------
// values tile: T[a,b] = fac * sum_m v[m,a]*v[m,b]   (lane = 8x4)
// Stores apply lane offsets (a0, b0) internally (FIX vs round 7).
// ---------------------------------------------------------------------------
__device__ __forceinline__ void values_tile(const float* __restrict__ base,
                                            int M, float fac, int a0, int b0,
                                            float* __restrict__ o) {
    float acc[8][4];
#pragma unroll
    for (int r = 0; r < 8; ++r)
#pragma unroll
        for (int c = 0; c < 4; ++c) acc[r][c] = 0.0f;

    for (int m = 0; m < M; ++m) {
        const float* row = base + m * 32;
        float4 a0v = *(const float4*)(row + a0);
        float4 a1v = *(const float4*)(row + a0 + 4);
        float4 bv  = *(const float4*)(row + b0);
        float av[8] = {a0v.x, a0v.y, a0v.z, a0v.w, a1v.x, a1v.y, a1v.z, a1v.w};
        float bb[4] = {bv.x, bv.y, bv.z, bv.w};
#pragma unroll
        for (int r = 0; r < 8; ++r)
#pragma unroll
            for (int c = 0; c < 4; ++c) acc[r][c] += av[r] * bb[c];
    }

#pragma unroll
    for (int r = 0; r < 8; ++r) {
        float4 s = make_float4(fac * acc[r][0], fac * acc[r][1],
                               fac * acc[r][2], fac * acc[r][3]);
        __stcs((float4*)(o + (a0 + r) * 32 + b0), s);
    }
}

// ---------------------------------------------------------------------------
// fused kernel: 96 threads (3 warps) per block.
//   bid <  NE : gradient entry e = bid            (one (i,x) pair)
//   bid >= NE : values sample i = bid - NE
// warp k handles l = 5-k then l = k  ->  12 m-steps per warp (balanced).
// ---------------------------------------------------------------------------
__global__ void __launch_bounds__(96, 10) fused_kernel(Ptrs p,
                                                       const int* __restrict__ gidx,
                                                       float* __restrict__ out) {
    __shared__ __align__(16) float sA[1152];
    __shared__ __align__(16) float sB[1152];
    const int bid = blockIdx.x;
    const int tid = threadIdx.x;
    const int k = tid >> 5;
    const int lane = tid & 31;
    const int a0 = (lane >> 3) * 8;
    const int b0 = (lane & 7) * 4;

    if (bid < NE) {
        const int e = bid;
        const int s = gidx[e / 3];
#pragma unroll
        for (int l = 0; l < 6; ++l) {
            const int cnt4 = (2 * l + 1) * 8;
            const float4* gs = (const float4*)(p.g[l] + (size_t)e * (2 * l + 1) * 32);
            const float4* vs = (const float4*)(p.v[l] + (size_t)s * (2 * l + 1) * 32);
            const float fac = FAC[l];
            float4* dg = (float4*)(sA + loff(l));
            float4* dv = (float4*)(sB + loff(l));
            for (int j = tid; j < cnt4; j += 96) {
                dg[j] = __ldcs(gs + j);            // read-once: stream past L2
                float4 t = vs[j];                  // reused across blocks: keep in L2
                dv[j] = make_float4(fac * t.x, fac * t.y, fac * t.z, fac * t.w);
            }
        }
        __syncthreads();

        float* obase = out + (size_t)NS * NSOAP + (size_t)e * NSOAP;
        {
            const int l = 5 - k;
            grads_tile(sA + loff(l), sB + loff(l), 2 * l + 1, a0, b0, obase + l * 1024);
        }
        {
            const int l = k;
            grads_tile(sA + loff(l), sB + loff(l), 2 * l + 1, a0, b0, obase + l * 1024);
        }
    } else {
        const int i = bid - NE;
#pragma unroll
        for (int l = 0; l < 6; ++l) {
            const int cnt4 = (2 * l + 1) * 8;
            const float4* src = (const float4*)(p.v[l] + (size_t)i * (2 * l + 1) * 32);
            float4* dst = (float4*)(sA + loff(l));
            for (int j = tid; j < cnt4; j += 96) dst[j] = src[j];
        }
        __syncthreads();

        float* obase = out + (size_t)i * NSOAP;
        {
            const int l = 5 - k;
            values_tile(sA + loff(l), 2 * l + 1, FAC[l], a0, b0, obase + l * 1024);
        }
        {
            const int l = k;
            values_tile(sA + loff(l), 2 * l + 1, FAC[l], a0, b0, obase + l * 1024);
        }
    }
}

// ---------------------------------------------------------------------------
extern "C" void kernel_launch(void* const* d_in, const int* in_sizes, int n_in,
                              void* d_out, int out_size) {
    Ptrs p;
    const int* gidx = nullptr;
    for (int k = 0; k < n_in; ++k) {
        const int sz = in_sizes[k];
        if (sz == NG) { gidx = (const int*)d_in[k]; continue; }
        for (int l = 0; l < 6; ++l) {
            const int M = 2 * l + 1;
            if (sz == NS * M * 32)          p.v[l] = (const float*)d_in[k];
            else if (sz == NG * 3 * M * 32) p.g[l] = (const float*)d_in[k];
        }
    }
    float* out = (float*)d_out;

    fused_kernel<<<NE + NS, 96>>>(p, gidx, out);
    (void)out_size;
}